// round 14
// baseline (speedup 1.0000x reference)
#include <cuda_runtime.h>
#include <cuda_fp16.h>
#include <math.h>
#include <stdint.h>

#define D_MODEL 1024
#define NHEAD   16
#define DH      64
#define SEQ     2048
#define BATCH   2
#define ROWS    (BATCH * SEQ)       // 4096
#define NBH     (BATCH * NHEAD)     // 32

// Q pre-scale: 0.125 * log2(e)  (softmax scale folded into Q, exp -> ex2)
#define QSCALE 0.18033688011112042f

// ---------------- scratch (static device arrays; no allocations) ----------------
__device__ __half g_xn[ROWS * D_MODEL];          // LN output (fp16)
__device__ __half g_wqkv[D_MODEL * 3 * D_MODEL]; // fp16 weights [K][N]
__device__ __half g_wout[D_MODEL * D_MODEL];     // fp16 weights [K][N]
__device__ __half g_qkv[ROWS * 3 * D_MODEL];     // QKV (fp16; Q pre-scaled)
__device__ __half g_ao[ROWS * D_MODEL];          // attn output (fp16)

__device__ __forceinline__ uint32_t pack_h2(float a, float b) {
    __half2 h = __floats2half2_rn(a, b);
    return *(uint32_t*)&h;
}
__device__ __forceinline__ uint32_t smem_u32(const void* p) {
    return (uint32_t)__cvta_generic_to_shared(p);
}
__device__ __forceinline__ float ex2f(float x) {
    float y;
    asm("ex2.approx.ftz.f32 %0, %1;" : "=f"(y) : "f"(x));
    return y;
}

#define MMA_F16(c, a, b0, b1)                                                      \
    asm volatile("mma.sync.aligned.m16n8k16.row.col.f32.f16.f16.f32 "              \
                 "{%0,%1,%2,%3}, {%4,%5,%6,%7}, {%8,%9}, {%0,%1,%2,%3};\n"         \
                 : "+f"((c)[0]), "+f"((c)[1]), "+f"((c)[2]), "+f"((c)[3])          \
                 : "r"((a)[0]), "r"((a)[1]), "r"((a)[2]), "r"((a)[3]),             \
                   "r"(b0), "r"(b1))

#define LDSM_X4(r0, r1, r2, r3, addr)                                              \
    asm volatile("ldmatrix.sync.aligned.m8n8.x4.shared.b16 {%0,%1,%2,%3}, [%4];"   \
                 : "=r"(r0), "=r"(r1), "=r"(r2), "=r"(r3) : "r"(addr))

#define LDSM_X4_T(r0, r1, r2, r3, addr)                                            \
    asm volatile("ldmatrix.sync.aligned.m8n8.x4.trans.shared.b16 {%0,%1,%2,%3}, [%4];" \
                 : "=r"(r0), "=r"(r1), "=r"(r2), "=r"(r3) : "r"(addr))

#define CP16(dst, src)                                                             \
    asm volatile("cp.async.cg.shared.global [%0], [%1], 16;" :: "r"(dst), "l"(src))
#define CP_COMMIT() asm volatile("cp.async.commit_group;" ::: "memory")
#define CP_WAIT1()  asm volatile("cp.async.wait_group 1;" ::: "memory")
#define CP_WAIT0()  asm volatile("cp.async.wait_group 0;" ::: "memory")

// ---------------- fp32 -> fp16 weight convert ----------------
__global__ void __launch_bounds__(256) cvt_kernel(const float* __restrict__ src,
                                                  __half* __restrict__ dst) {
    size_t i = ((size_t)blockIdx.x * 256 + threadIdx.x) * 8;
    float4 v0 = *(const float4*)(src + i);
    float4 v1 = *(const float4*)(src + i + 4);
    uint4 h;
    h.x = pack_h2(v0.x, v0.y);
    h.y = pack_h2(v0.z, v0.w);
    h.z = pack_h2(v1.x, v1.y);
    h.w = pack_h2(v1.z, v1.w);
    *(uint4*)(dst + i) = h;
}

// ---------------- LayerNorm (fp16 out) ----------------
__global__ void __launch_bounds__(256) ln_kernel(const float* __restrict__ x,
                                                 const float* __restrict__ gamma,
                                                 const float* __restrict__ beta) {
    int row = blockIdx.x;
    int tid = threadIdx.x;
    const float4* xr = (const float4*)(x + (size_t)row * D_MODEL);
    float4 v = xr[tid];
    float s  = v.x + v.y + v.z + v.w;
    float ss = v.x * v.x + v.y * v.y + v.z * v.z + v.w * v.w;

    __shared__ float reds[8], redss[8], bcast[2];
    for (int o = 16; o; o >>= 1) {
        s  += __shfl_down_sync(0xFFFFFFFFu, s, o);
        ss += __shfl_down_sync(0xFFFFFFFFu, ss, o);
    }
    int wid = tid >> 5, lid = tid & 31;
    if (lid == 0) { reds[wid] = s; redss[wid] = ss; }
    __syncthreads();
    if (tid == 0) {
        float ts = 0.f, tss = 0.f;
        for (int i = 0; i < 8; i++) { ts += reds[i]; tss += redss[i]; }
        float mu  = ts * (1.0f / D_MODEL);
        float var = tss * (1.0f / D_MODEL) - mu * mu;
        bcast[0] = mu;
        bcast[1] = rsqrtf(var + 1e-5f);
    }
    __syncthreads();
    float mu = bcast[0], r = bcast[1];
    float4 gg = ((const float4*)gamma)[tid];
    float4 bb = ((const float4*)beta)[tid];
    uint2 hh;
    hh.x = pack_h2((v.x - mu) * r * gg.x + bb.x, (v.y - mu) * r * gg.y + bb.y);
    hh.y = pack_h2((v.z - mu) * r * gg.z + bb.z, (v.w - mu) * r * gg.w + bb.w);
    ((uint2*)(g_xn + (size_t)row * D_MODEL))[tid] = hh;
}

// ---------------- fp16 tensor-core GEMM, BK=64, 3-stage cp.async ----------------
// BM=BN=128, BK=64, 256 threads = 8 warps (2x4), warp tile 64x32, m16n8k16.
#define GA_PITCH 72                      // halves (144B rows, conflict-free LDSM)
#define GB_PITCH 136                     // halves (272B rows, conflict-free trans LDSM)
#define GA_HALF  (128 * GA_PITCH)        // 9216 halves
#define GB_HALF  (64 * GB_PITCH)         // 8704 halves
#define STG_HALF (GA_HALF + GB_HALF)     // per-stage halves
#define STG_B    (STG_HALF * 2)          // per-stage bytes (35840)
#define GEMM_SMEM (3 * STG_B)            // 107520 B

template <int HALF_OUT>
__global__ void __launch_bounds__(256) gemm_f16(const __half* __restrict__ A,
                                                const __half* __restrict__ B,
                                                void* __restrict__ Cv,
                                                int M, int N, int K) {
    extern __shared__ __half smg[];

    int tid  = threadIdx.x;
    int warp = tid >> 5, lane = tid & 31;
    int wm = warp >> 2, wn = warp & 3;
    int g  = lane >> 2, t4 = lane & 3;
    int l8 = lane & 7, seg = lane >> 3;
    int bm = blockIdx.y * 128, bn = blockIdx.x * 128;

    float acc[4][4][4];
#pragma unroll
    for (int f = 0; f < 4; f++)
#pragma unroll
        for (int q = 0; q < 4; q++)
#pragma unroll
            for (int i = 0; i < 4; i++) acc[f][q][i] = 0.f;

    // load roles
    int arow = tid >> 1;             // 0..127
    int acol = (tid & 1) * 32;       // halves
    int brow = tid >> 2;             // 0..63
    int bcol = (tid & 3) * 32;       // halves
    const __half* Ap = A + (size_t)(bm + arow) * K + acol;
    const __half* Bp = B + (size_t)brow * N + bn + bcol;

    uint32_t sm0 = smem_u32(smg);
    uint32_t as_dst = sm0 + (arow * GA_PITCH + acol) * 2;
    uint32_t bs_dst = sm0 + GA_HALF * 2 + (brow * GB_PITCH + bcol) * 2;

    auto issue = [&](int kt, int buf) {
        const __half* Ap2 = Ap + kt * 64;
        const __half* Bp2 = Bp + (size_t)kt * 64 * N;
        uint32_t ad = as_dst + buf * STG_B;
        uint32_t bd = bs_dst + buf * STG_B;
#pragma unroll
        for (int j = 0; j < 4; j++) {
            CP16(ad + j * 16, Ap2 + j * 8);
            CP16(bd + j * 16, Bp2 + j * 8);
        }
    };

    issue(0, 0); CP_COMMIT();
    issue(1, 1); CP_COMMIT();

    uint32_t a_base_off = ((wm * 64 + (seg & 1) * 8 + l8) * GA_PITCH + (seg >> 1) * 8) * 2;
    uint32_t b_base_off = (((seg & 1) * 8 + l8) * GB_PITCH + wn * 32 + (seg >> 1) * 8) * 2;

    int NT = K >> 6;                 // 16
    int cur = 0, nxt2 = 2;
    for (int kt = 0; kt < NT; kt++) {
        if (kt + 1 < NT) CP_WAIT1(); else CP_WAIT0();
        __syncthreads();
        if (kt + 2 < NT) { issue(kt + 2, nxt2); CP_COMMIT(); }

        uint32_t a_addr = sm0 + cur * STG_B + a_base_off;
        uint32_t b_addr = sm0 + GA_HALF * 2 + cur * STG_B + b_base_off;
#pragma unroll
        for (int ks = 0; ks < 4; ks++) {
            uint32_t af[4][4], bf[2][4];
#pragma unroll
            for (int f = 0; f < 4; f++)
                LDSM_X4(af[f][0], af[f][1], af[f][2], af[f][3],
                        a_addr + (f * 16 * GA_PITCH + ks * 16) * 2);
#pragma unroll
            for (int qq = 0; qq < 2; qq++)
                LDSM_X4_T(bf[qq][0], bf[qq][1], bf[qq][2], bf[qq][3],
                          b_addr + (ks * 16 * GB_PITCH + qq * 16) * 2);
#pragma unroll
            for (int f = 0; f < 4; f++)
#pragma unroll
                for (int q = 0; q < 4; q++)
                    MMA_F16(acc[f][q], af[f], bf[q >> 1][(q & 1) * 2],
                            bf[q >> 1][(q & 1) * 2 + 1]);
        }
        cur = (cur == 2) ? 0 : cur + 1;
        nxt2 = (nxt2 == 2) ? 0 : nxt2 + 1;
    }

    // epilogue (Q columns pre-scaled by QSCALE for the QKV GEMM)
    float cs = 1.0f;
    if (HALF_OUT && bn < 1024) cs = QSCALE;
#pragma unroll
    for (int f = 0; f < 4; f++) {
        int r0 = bm + wm * 64 + f * 16 + g;
#pragma unroll
        for (int q = 0; q < 4; q++) {
            int c = bn + wn * 32 + q * 8 + t4 * 2;
            if (HALF_OUT) {
                __half* C = (__half*)Cv;
                *(uint32_t*)&C[(size_t)r0 * N + c] =
                    pack_h2(acc[f][q][0] * cs, acc[f][q][1] * cs);
                *(uint32_t*)&C[(size_t)(r0 + 8) * N + c] =
                    pack_h2(acc[f][q][2] * cs, acc[f][q][3] * cs);
            } else {
                float* C = (float*)Cv;
                *(float2*)&C[(size_t)r0 * N + c] = make_float2(acc[f][q][0], acc[f][q][1]);
                *(float2*)&C[(size_t)(r0 + 8) * N + c] =
                    make_float2(acc[f][q][2], acc[f][q][3]);
            }
        }
    }
}

// ---------------- fp16 two-pass attention, 3-stage cp.async K/V pipeline ----------
// Q pre-scaled by QSCALE -> p = ex2(sacc) directly.
#define HPITCH 72
#define QH_SZ  (128 * HPITCH)
#define KH_SZ  (64 * HPITCH)
#define VH_SZ  (64 * HPITCH)
#define ATT_SMEM ((QH_SZ + 3 * KH_SZ + 3 * VH_SZ) * 2)

__global__ void __launch_bounds__(256, 2) attn_tc(float* __restrict__ attn) {
    extern __shared__ __half smh[];
    __half* Qh = smh;
    __half* Kh = smh + QH_SZ;
    __half* Vh = Kh + 3 * KH_SZ;

    int it = blockIdx.x;
    int bh = blockIdx.y;
    int b = bh >> 4, h = bh & 15;
    int tid = threadIdx.x;
    int warp = tid >> 5, lane = tid & 31;
    int g = lane >> 2, t4 = lane & 3;
    int l8 = lane & 7, seg = lane >> 3;

    size_t qkv_b = (size_t)(b * SEQ) * 3072;

    {
        int r  = tid >> 1;
        int c0 = (tid & 1) * 32;
        const __half* src = g_qkv + qkv_b + (size_t)(it * 128 + r) * 3072 + h * 64 + c0;
        __half* dst = Qh + r * HPITCH + c0;
#pragma unroll
        for (int c = 0; c < 32; c += 8)
            *(uint4*)(dst + c) = *(const uint4*)(src + c);
    }

    int ldr = tid >> 3;
    int ldc = (tid & 7) * 8;
    const __half* Kbase = g_qkv + qkv_b + 1024 + h * 64;
    const __half* Vbase = g_qkv + qkv_b + 2048 + h * 64;

    uint32_t k_dst = smem_u32(Kh) + (ldr * HPITCH + ldc) * 2;
    uint32_t v_dst = smem_u32(Vh) + (ldr * HPITCH + ldc) * 2;

    auto issueK = [&](int jt, int buf) {
        const __half* src = Kbase + (size_t)(jt * 64 + ldr) * 3072 + ldc;
        uint32_t d = k_dst + buf * KH_SZ * 2;
        CP16(d, src);
        CP16(d + 32 * HPITCH * 2, src + (size_t)32 * 3072);
    };
    auto issueV = [&](int jt, int buf) {
        const __half* src = Vbase + (size_t)(jt * 64 + ldr) * 3072 + ldc;
        uint32_t d = v_dst + buf * VH_SZ * 2;
        CP16(d, src);
        CP16(d + 32 * HPITCH * 2, src + (size_t)32 * 3072);
    };

    int q_off = (warp * 16 + (seg & 1) * 8 + l8) * HPITCH + (seg >> 1) * 8;
    int k_off = ((seg >> 1) * 8 + l8) * HPITCH + (seg & 1) * 8;
    int v_off = ((seg & 1) * 8 + l8) * HPITCH + (seg >> 1) * 8;
    uint32_t q_addr = smem_u32(Qh) + q_off * 2;

    // ======== Phase A: row sums ========
    issueK(0, 0); CP_COMMIT();
    issueK(1, 1); CP_COMMIT();

    float lsum0 = 0.f, lsum1 = 0.f;
    int cur = 0, nxt2 = 2;

#pragma unroll 1
    for (int jt = 0; jt < 32; jt++) {
        if (jt + 1 < 32) CP_WAIT1(); else CP_WAIT0();
        __syncthreads();
        if (jt + 2 < 32) { issueK(jt + 2, nxt2); CP_COMMIT(); }

        uint32_t k_addr = smem_u32(Kh) + cur * KH_SZ * 2 + k_off * 2;
        float sacc[8][4];
#pragma unroll
        for (int s = 0; s < 8; s++)
#pragma unroll
            for (int i = 0; i < 4; i++) sacc[s][i] = 0.f;

#pragma unroll
        for (int ks = 0; ks < 4; ks++) {
            uint32_t qa[4];
            LDSM_X4(qa[0], qa[1], qa[2], qa[3], q_addr + ks * 32);
#pragma unroll
            for (int np = 0; np < 4; np++) {
                uint32_t kb[4];
                LDSM_X4(kb[0], kb[1], kb[2], kb[3],
                        k_addr + np * (16 * HPITCH * 2) + ks * 32);
                MMA_F16(sacc[np * 2],     qa, kb[0], kb[1]);
                MMA_F16(sacc[np * 2 + 1], qa, kb[2], kb[3]);
            }
        }
#pragma unroll
        for (int s = 0; s < 8; s++) {
            lsum0 += ex2f(sacc[s][0]) + ex2f(sacc[s][1]);
            lsum1 += ex2f(sacc[s][2]) + ex2f(sacc[s][3]);
        }
        cur = (cur == 2) ? 0 : cur + 1;
        nxt2 = (nxt2 == 2) ? 0 : nxt2 + 1;
    }

    lsum0 += __shfl_xor_sync(0xFFFFFFFFu, lsum0, 1);
    lsum0 += __shfl_xor_sync(0xFFFFFFFFu, lsum0, 2);
    lsum1 += __shfl_xor_sync(0xFFFFFFFFu, lsum1, 1);
    lsum1 += __shfl_xor_sync(0xFFFFFFFFu, lsum1, 2);
    float inv0 = 1.0f / lsum0;
    float inv1 = 1.0f / lsum1;

    __syncthreads();

    // ======== Phase B: normalized store + PV ========
    issueK(0, 0); issueV(0, 0); CP_COMMIT();
    issueK(1, 1); issueV(1, 1); CP_COMMIT();

    float oacc[8][4];
#pragma unroll
    for (int s = 0; s < 8; s++)
#pragma unroll
        for (int i = 0; i < 4; i++) oacc[s][i] = 0.f;

    cur = 0; nxt2 = 2;
#pragma unroll 1
    for (int jt = 0; jt < 32; jt++) {
        if (jt + 1 < 32) CP_WAIT1(); else CP_WAIT0();
        __syncthreads();
        if (jt + 2 < 32) { issueK(jt + 2, nxt2); issueV(jt + 2, nxt2); CP_COMMIT(); }

        uint32_t k_addr = smem_u32(Kh) + cur * KH_SZ * 2 + k_off * 2;
        uint32_t v_addr = smem_u32(Vh) + cur * VH_SZ * 2 + v_off * 2;

        float sacc[8][4];
#pragma unroll
        for (int s = 0; s < 8; s++)
#pragma unroll
            for (int i = 0; i < 4; i++) sacc[s][i] = 0.f;

#pragma unroll
        for (int ks = 0; ks < 4; ks++) {
            uint32_t qa[4];
            LDSM_X4(qa[0], qa[1], qa[2], qa[3], q_addr + ks * 32);
#pragma unroll
            for (int np = 0; np < 4; np++) {
                uint32_t kb[4];
                LDSM_X4(kb[0], kb[1], kb[2], kb[3],
                        k_addr + np * (16 * HPITCH * 2) + ks * 32);
                MMA_F16(sacc[np * 2],     qa, kb[0], kb[1]);
                MMA_F16(sacc[np * 2 + 1], qa, kb[2], kb[3]);
            }
        }

        size_t abase = ((size_t)bh * SEQ + (size_t)(it * 128 + warp * 16)) * SEQ
                     + (size_t)jt * 64;
        uint32_t pa[4][4];
#pragma unroll
        for (int s = 0; s < 8; s++) {
            float p0 = ex2f(sacc[s][0]) * inv0;
            float p1 = ex2f(sacc[s][1]) * inv0;
            float p2 = ex2f(sacc[s][2]) * inv1;
            float p3 = ex2f(sacc[s][3]) * inv1;
            int cl = s * 8 + t4 * 2;
            *(float2*)(attn + abase + (size_t)g * SEQ + cl)       = make_float2(p0, p1);
            *(float2*)(attn + abase + (size_t)(g + 8) * SEQ + cl) = make_float2(p2, p3);
            int ks = s >> 1;
            if ((s & 1) == 0) {
                pa[ks][0] = pack_h2(p0, p1);
                pa[ks][1] = pack_h2(p2, p3);
            } else {
                pa[ks][2] = pack_h2(p0, p1);
                pa[ks][3] = pack_h2(p2, p3);
            }
        }

#pragma unroll
        for (int ks = 0; ks < 4; ks++) {
#pragma unroll
            for (int np = 0; np < 4; np++) {
                uint32_t vb[4];
                LDSM_X4_T(vb[0], vb[1], vb[2], vb[3],
                          v_addr + ks * (16 * HPITCH * 2) + np * 32);
                MMA_F16(oacc[np * 2],     pa[ks], vb[0], vb[1]);
                MMA_F16(oacc[np * 2 + 1], pa[ks], vb[2], vb[3]);
            }
        }
        cur = (cur == 2) ? 0 : cur + 1;
        nxt2 = (nxt2 == 2) ? 0 : nxt2 + 1;
    }

    int row0 = it * 128 + warp * 16 + g;
    size_t obase0 = (size_t)(b * SEQ + row0) * D_MODEL + h * 64;
    size_t obase1 = obase0 + (size_t)8 * D_MODEL;
#pragma unroll
    for (int s = 0; s < 8; s++) {
        int cl = s * 8 + t4 * 2;
        *(uint32_t*)(g_ao + obase0 + cl) = pack_h2(oacc[s][0], oacc[s][1]);
        *(uint32_t*)(g_ao + obase1 + cl) = pack_h2(oacc[s][2], oacc[s][3]);
    }
}

// ---------------- launch ----------------
extern "C" void kernel_launch(void* const* d_in, const int* in_sizes, int n_in,
                              void* d_out, int out_size) {
    const float* x     = (const float*)d_in[0];
    const float* gamma = (const float*)d_in[1];
    const float* beta  = (const float*)d_in[2];
    const float* Wqkv  = (const float*)d_in[3];
    const float* Wout  = (const float*)d_in[4];
    float* out  = (float*)d_out;
    float* attn = out + (size_t)ROWS * D_MODEL;

    __half *p_xn, *p_wqkv, *p_wout, *p_qkv, *p_ao;
    cudaGetSymbolAddress((void**)&p_xn,   g_xn);
    cudaGetSymbolAddress((void**)&p_wqkv, g_wqkv);
    cudaGetSymbolAddress((void**)&p_wout, g_wout);
    cudaGetSymbolAddress((void**)&p_qkv,  g_qkv);
    cudaGetSymbolAddress((void**)&p_ao,   g_ao);

    cudaFuncSetAttribute(attn_tc, cudaFuncAttributeMaxDynamicSharedMemorySize, ATT_SMEM);
    cudaFuncSetAttribute(gemm_f16<1>, cudaFuncAttributeMaxDynamicSharedMemorySize, GEMM_SMEM);
    cudaFuncSetAttribute(gemm_f16<0>, cudaFuncAttributeMaxDynamicSharedMemorySize, GEMM_SMEM);

    // 1) LayerNorm (fp16 out) + weight converts
    ln_kernel<<<ROWS, 256>>>(x, gamma, beta);
    cvt_kernel<<<(D_MODEL * 3 * D_MODEL) / (256 * 8), 256>>>(Wqkv, p_wqkv);
    cvt_kernel<<<(D_MODEL * D_MODEL) / (256 * 8), 256>>>(Wout, p_wout);
    // 2) QKV GEMM (fp16 MMA, fp16 out, BK=64 3-stage; Q cols pre-scaled)
    gemm_f16<1><<<dim3(3 * D_MODEL / 128, ROWS / 128), 256, GEMM_SMEM>>>(
        p_xn, p_wqkv, p_qkv, ROWS, 3 * D_MODEL, D_MODEL);
    // 3) two-pass fp16 attention (normalized attn + O; ex2 softmax)
    attn_tc<<<dim3(SEQ / 128, NBH), 256, ATT_SMEM>>>(attn);
    // 4) out projection (fp16 MMA, fp32 out)
    gemm_f16<0><<<dim3(D_MODEL / 128, ROWS / 128), 256, GEMM_SMEM>>>(
        p_ao, p_wout, out, ROWS, D_MODEL, D_MODEL);
}

// round 15
// speedup vs baseline: 1.1399x; 1.1399x over previous
#include <cuda_runtime.h>
#include <cuda_fp16.h>
#include <math.h>
#include <stdint.h>

#define D_MODEL 1024
#define NHEAD   16
#define DH      64
#define SEQ     2048
#define BATCH   2
#define ROWS    (BATCH * SEQ)       // 4096
#define NBH     (BATCH * NHEAD)     // 32

// Q pre-scale: 0.125 * log2(e)  (softmax scale folded into Q, exp -> ex2)
#define QSCALE 0.18033688011112042f

// ---------------- scratch (static device arrays; no allocations) ----------------
__device__ __half g_xn[ROWS * D_MODEL];          // LN output (fp16)
__device__ __half g_wqkv[D_MODEL * 3 * D_MODEL]; // fp16 weights [K][N]
__device__ __half g_wout[D_MODEL * D_MODEL];     // fp16 weights [K][N]
__device__ __half g_qkv[ROWS * 3 * D_MODEL];     // QKV (fp16; Q pre-scaled)
__device__ __half g_ao[ROWS * D_MODEL];          // attn output (fp16)

__device__ __forceinline__ uint32_t pack_h2(float a, float b) {
    __half2 h = __floats2half2_rn(a, b);
    return *(uint32_t*)&h;
}
__device__ __forceinline__ uint32_t smem_u32(const void* p) {
    return (uint32_t)__cvta_generic_to_shared(p);
}
__device__ __forceinline__ float ex2f(float x) {
    float y;
    asm("ex2.approx.ftz.f32 %0, %1;" : "=f"(y) : "f"(x));
    return y;
}

#define MMA_F16(c, a, b0, b1)                                                      \
    asm volatile("mma.sync.aligned.m16n8k16.row.col.f32.f16.f16.f32 "              \
                 "{%0,%1,%2,%3}, {%4,%5,%6,%7}, {%8,%9}, {%0,%1,%2,%3};\n"         \
                 : "+f"((c)[0]), "+f"((c)[1]), "+f"((c)[2]), "+f"((c)[3])          \
                 : "r"((a)[0]), "r"((a)[1]), "r"((a)[2]), "r"((a)[3]),             \
                   "r"(b0), "r"(b1))

#define LDSM_X4(r0, r1, r2, r3, addr)                                              \
    asm volatile("ldmatrix.sync.aligned.m8n8.x4.shared.b16 {%0,%1,%2,%3}, [%4];"   \
                 : "=r"(r0), "=r"(r1), "=r"(r2), "=r"(r3) : "r"(addr))

#define LDSM_X4_T(r0, r1, r2, r3, addr)                                            \
    asm volatile("ldmatrix.sync.aligned.m8n8.x4.trans.shared.b16 {%0,%1,%2,%3}, [%4];" \
                 : "=r"(r0), "=r"(r1), "=r"(r2), "=r"(r3) : "r"(addr))

#define CP16(dst, src)                                                             \
    asm volatile("cp.async.cg.shared.global [%0], [%1], 16;" :: "r"(dst), "l"(src))
#define CP_COMMIT() asm volatile("cp.async.commit_group;" ::: "memory")
#define CP_WAIT1()  asm volatile("cp.async.wait_group 1;" ::: "memory")
#define CP_WAIT0()  asm volatile("cp.async.wait_group 0;" ::: "memory")

// ---------------- fp32 -> fp16 weight convert ----------------
__global__ void __launch_bounds__(256) cvt_kernel(const float* __restrict__ src,
                                                  __half* __restrict__ dst) {
    size_t i = ((size_t)blockIdx.x * 256 + threadIdx.x) * 8;
    float4 v0 = *(const float4*)(src + i);
    float4 v1 = *(const float4*)(src + i + 4);
    uint4 h;
    h.x = pack_h2(v0.x, v0.y);
    h.y = pack_h2(v0.z, v0.w);
    h.z = pack_h2(v1.x, v1.y);
    h.w = pack_h2(v1.z, v1.w);
    *(uint4*)(dst + i) = h;
}

// ---------------- LayerNorm (fp16 out) ----------------
__global__ void __launch_bounds__(256) ln_kernel(const float* __restrict__ x,
                                                 const float* __restrict__ gamma,
                                                 const float* __restrict__ beta) {
    int row = blockIdx.x;
    int tid = threadIdx.x;
    const float4* xr = (const float4*)(x + (size_t)row * D_MODEL);
    float4 v = xr[tid];
    float s  = v.x + v.y + v.z + v.w;
    float ss = v.x * v.x + v.y * v.y + v.z * v.z + v.w * v.w;

    __shared__ float reds[8], redss[8], bcast[2];
    for (int o = 16; o; o >>= 1) {
        s  += __shfl_down_sync(0xFFFFFFFFu, s, o);
        ss += __shfl_down_sync(0xFFFFFFFFu, ss, o);
    }
    int wid = tid >> 5, lid = tid & 31;
    if (lid == 0) { reds[wid] = s; redss[wid] = ss; }
    __syncthreads();
    if (tid == 0) {
        float ts = 0.f, tss = 0.f;
        for (int i = 0; i < 8; i++) { ts += reds[i]; tss += redss[i]; }
        float mu  = ts * (1.0f / D_MODEL);
        float var = tss * (1.0f / D_MODEL) - mu * mu;
        bcast[0] = mu;
        bcast[1] = rsqrtf(var + 1e-5f);
    }
    __syncthreads();
    float mu = bcast[0], r = bcast[1];
    float4 gg = ((const float4*)gamma)[tid];
    float4 bb = ((const float4*)beta)[tid];
    uint2 hh;
    hh.x = pack_h2((v.x - mu) * r * gg.x + bb.x, (v.y - mu) * r * gg.y + bb.y);
    hh.y = pack_h2((v.z - mu) * r * gg.z + bb.z, (v.w - mu) * r * gg.w + bb.w);
    ((uint2*)(g_xn + (size_t)row * D_MODEL))[tid] = hh;
}

// ---------------- fp16 tensor-core GEMM, BK=32, 3-stage cp.async (R12 config) ----
#define APITCH 40
#define BPITCH 136
#define AS_STG (128 * APITCH)
#define BS_STG (32 * BPITCH)
#define GEMM_SMEM ((3 * AS_STG + 3 * BS_STG) * 2)

template <int HALF_OUT>
__global__ void __launch_bounds__(256, 2) gemm_f16(const __half* __restrict__ A,
                                                   const __half* __restrict__ B,
                                                   void* __restrict__ Cv,
                                                   int M, int N, int K) {
    extern __shared__ __half smg[];
    __half* As = smg;                 // [3][128*APITCH]
    __half* Bs = smg + 3 * AS_STG;    // [3][32*BPITCH]

    int tid  = threadIdx.x;
    int warp = tid >> 5, lane = tid & 31;
    int wm = warp >> 2, wn = warp & 3;
    int g  = lane >> 2, t4 = lane & 3;
    int l8 = lane & 7, seg = lane >> 3;
    int bm = blockIdx.y * 128, bn = blockIdx.x * 128;

    float acc[4][4][4];
#pragma unroll
    for (int f = 0; f < 4; f++)
#pragma unroll
        for (int q = 0; q < 4; q++)
#pragma unroll
            for (int i = 0; i < 4; i++) acc[f][q][i] = 0.f;

    int ar0 = tid >> 2;            // 0..63
    int ac0 = (tid & 3) * 8;       // 0..24
    int br0 = tid >> 4;            // 0..15
    int bc0 = (tid & 15) * 8;      // 0..120
    const __half* Ap = A + (size_t)(bm + ar0) * K + ac0;
    const __half* Bp = B + (size_t)br0 * N + bn + bc0;

    uint32_t as_dst = smem_u32(As) + (ar0 * APITCH + ac0) * 2;
    uint32_t bs_dst = smem_u32(Bs) + (br0 * BPITCH + bc0) * 2;

    auto issue = [&](int kt, int buf) {
        const __half* Ap2 = Ap + kt * 32;
        const __half* Bp2 = Bp + (size_t)kt * 32 * N;
        uint32_t ad = as_dst + buf * AS_STG * 2;
        uint32_t bd = bs_dst + buf * BS_STG * 2;
        CP16(ad, Ap2);
        CP16(ad + 64 * APITCH * 2, Ap2 + (size_t)64 * K);
        CP16(bd, Bp2);
        CP16(bd + 16 * BPITCH * 2, Bp2 + (size_t)16 * N);
    };

    issue(0, 0); CP_COMMIT();
    issue(1, 1); CP_COMMIT();

    uint32_t a_base_off = ((wm * 64 + (seg & 1) * 8 + l8) * APITCH + (seg >> 1) * 8) * 2;
    uint32_t b_base_off = (((seg & 1) * 8 + l8) * BPITCH + wn * 32 + (seg >> 1) * 8) * 2;

    int NT = K >> 5;
    int cur = 0, nxt2 = 2;
    for (int kt = 0; kt < NT; kt++) {
        if (kt + 1 < NT) CP_WAIT1(); else CP_WAIT0();
        __syncthreads();
        if (kt + 2 < NT) { issue(kt + 2, nxt2); CP_COMMIT(); }

        uint32_t a_addr = smem_u32(As) + cur * AS_STG * 2 + a_base_off;
        uint32_t b_addr = smem_u32(Bs) + cur * BS_STG * 2 + b_base_off;
#pragma unroll
        for (int ks = 0; ks < 2; ks++) {
            uint32_t af[4][4], bf[2][4];
#pragma unroll
            for (int f = 0; f < 4; f++)
                LDSM_X4(af[f][0], af[f][1], af[f][2], af[f][3],
                        a_addr + (f * 16 * APITCH + ks * 16) * 2);
#pragma unroll
            for (int qq = 0; qq < 2; qq++)
                LDSM_X4_T(bf[qq][0], bf[qq][1], bf[qq][2], bf[qq][3],
                          b_addr + (ks * 16 * BPITCH + qq * 16) * 2);
#pragma unroll
            for (int f = 0; f < 4; f++)
#pragma unroll
                for (int q = 0; q < 4; q++)
                    MMA_F16(acc[f][q], af[f], bf[q >> 1][(q & 1) * 2],
                            bf[q >> 1][(q & 1) * 2 + 1]);
        }
        cur = (cur == 2) ? 0 : cur + 1;
        nxt2 = (nxt2 == 2) ? 0 : nxt2 + 1;
    }

    // epilogue (Q columns pre-scaled by QSCALE for the QKV GEMM)
    float cs = 1.0f;
    if (HALF_OUT && bn < 1024) cs = QSCALE;
#pragma unroll
    for (int f = 0; f < 4; f++) {
        int r0 = bm + wm * 64 + f * 16 + g;
#pragma unroll
        for (int q = 0; q < 4; q++) {
            int c = bn + wn * 32 + q * 8 + t4 * 2;
            if (HALF_OUT) {
                __half* C = (__half*)Cv;
                *(uint32_t*)&C[(size_t)r0 * N + c] =
                    pack_h2(acc[f][q][0] * cs, acc[f][q][1] * cs);
                *(uint32_t*)&C[(size_t)(r0 + 8) * N + c] =
                    pack_h2(acc[f][q][2] * cs, acc[f][q][3] * cs);
            } else {
                float* C = (float*)Cv;
                *(float2*)&C[(size_t)r0 * N + c] = make_float2(acc[f][q][0], acc[f][q][1]);
                *(float2*)&C[(size_t)(r0 + 8) * N + c] =
                    make_float2(acc[f][q][2], acc[f][q][3]);
            }
        }
    }
}

// ---------------- fp16 two-pass attention, 2-stage cp.async, 2 CTAs/SM ----------
// Q pre-scaled -> p = ex2(sacc). smem 55.3 KB -> occupancy 2.
#define HPITCH 72
#define QH_SZ  (128 * HPITCH)
#define KH_SZ  (64 * HPITCH)
#define VH_SZ  (64 * HPITCH)
#define ATT_SMEM ((QH_SZ + 2 * KH_SZ + 2 * VH_SZ) * 2)

__global__ void __launch_bounds__(256, 2) attn_tc(float* __restrict__ attn) {
    extern __shared__ __half smh[];
    __half* Qh = smh;                    // [128][72]
    __half* Kh = smh + QH_SZ;            // [2][64][72]
    __half* Vh = Kh + 2 * KH_SZ;         // [2][64][72]

    int it = blockIdx.x;
    int bh = blockIdx.y;
    int b = bh >> 4, h = bh & 15;
    int tid = threadIdx.x;
    int warp = tid >> 5, lane = tid & 31;
    int g = lane >> 2, t4 = lane & 3;
    int l8 = lane & 7, seg = lane >> 3;

    size_t qkv_b = (size_t)(b * SEQ) * 3072;

    // stage Q tile [128][64]
    {
        int r  = tid >> 1;
        int c0 = (tid & 1) * 32;
        const __half* src = g_qkv + qkv_b + (size_t)(it * 128 + r) * 3072 + h * 64 + c0;
        __half* dst = Qh + r * HPITCH + c0;
#pragma unroll
        for (int c = 0; c < 32; c += 8)
            *(uint4*)(dst + c) = *(const uint4*)(src + c);
    }

    int ldr = tid >> 3;
    int ldc = (tid & 7) * 8;
    const __half* Kbase = g_qkv + qkv_b + 1024 + h * 64;
    const __half* Vbase = g_qkv + qkv_b + 2048 + h * 64;

    uint32_t k_dst = smem_u32(Kh) + (ldr * HPITCH + ldc) * 2;
    uint32_t v_dst = smem_u32(Vh) + (ldr * HPITCH + ldc) * 2;

    auto issueK = [&](int jt, int buf) {
        const __half* src = Kbase + (size_t)(jt * 64 + ldr) * 3072 + ldc;
        uint32_t d = k_dst + buf * KH_SZ * 2;
        CP16(d, src);
        CP16(d + 32 * HPITCH * 2, src + (size_t)32 * 3072);
    };
    auto issueV = [&](int jt, int buf) {
        const __half* src = Vbase + (size_t)(jt * 64 + ldr) * 3072 + ldc;
        uint32_t d = v_dst + buf * VH_SZ * 2;
        CP16(d, src);
        CP16(d + 32 * HPITCH * 2, src + (size_t)32 * 3072);
    };

    int q_off = (warp * 16 + (seg & 1) * 8 + l8) * HPITCH + (seg >> 1) * 8;
    int k_off = ((seg >> 1) * 8 + l8) * HPITCH + (seg & 1) * 8;
    int v_off = ((seg & 1) * 8 + l8) * HPITCH + (seg >> 1) * 8;
    uint32_t q_addr = smem_u32(Qh) + q_off * 2;

    // ======== Phase A: row sums (K only) ========
    issueK(0, 0); CP_COMMIT();
    issueK(1, 1); CP_COMMIT();

    float lsum0 = 0.f, lsum1 = 0.f;

#pragma unroll 1
    for (int jt = 0; jt < 32; jt++) {
        int cur = jt & 1;
        if (jt + 1 < 32) CP_WAIT1(); else CP_WAIT0();
        __syncthreads();

        uint32_t k_addr = smem_u32(Kh) + cur * KH_SZ * 2 + k_off * 2;
        float sacc[8][4];
#pragma unroll
        for (int s = 0; s < 8; s++)
#pragma unroll
            for (int i = 0; i < 4; i++) sacc[s][i] = 0.f;

#pragma unroll
        for (int ks = 0; ks < 4; ks++) {
            uint32_t qa[4];
            LDSM_X4(qa[0], qa[1], qa[2], qa[3], q_addr + ks * 32);
#pragma unroll
            for (int np = 0; np < 4; np++) {
                uint32_t kb[4];
                LDSM_X4(kb[0], kb[1], kb[2], kb[3],
                        k_addr + np * (16 * HPITCH * 2) + ks * 32);
                MMA_F16(sacc[np * 2],     qa, kb[0], kb[1]);
                MMA_F16(sacc[np * 2 + 1], qa, kb[2], kb[3]);
            }
        }
#pragma unroll
        for (int s = 0; s < 8; s++) {
            lsum0 += ex2f(sacc[s][0]) + ex2f(sacc[s][1]);
            lsum1 += ex2f(sacc[s][2]) + ex2f(sacc[s][3]);
        }
        __syncthreads();
        if (jt + 2 < 32) { issueK(jt + 2, cur); CP_COMMIT(); }
    }

    lsum0 += __shfl_xor_sync(0xFFFFFFFFu, lsum0, 1);
    lsum0 += __shfl_xor_sync(0xFFFFFFFFu, lsum0, 2);
    lsum1 += __shfl_xor_sync(0xFFFFFFFFu, lsum1, 1);
    lsum1 += __shfl_xor_sync(0xFFFFFFFFu, lsum1, 2);
    float inv0 = 1.0f / lsum0;
    float inv1 = 1.0f / lsum1;

    __syncthreads();

    // ======== Phase B: normalized store + PV ========
    issueK(0, 0); issueV(0, 0); CP_COMMIT();
    issueK(1, 1); issueV(1, 1); CP_COMMIT();

    float oacc[8][4];
#pragma unroll
    for (int s = 0; s < 8; s++)
#pragma unroll
        for (int i = 0; i < 4; i++) oacc[s][i] = 0.f;

#pragma unroll 1
    for (int jt = 0; jt < 32; jt++) {
        int cur = jt & 1;
        if (jt + 1 < 32) CP_WAIT1(); else CP_WAIT0();
        __syncthreads();

        uint32_t k_addr = smem_u32(Kh) + cur * KH_SZ * 2 + k_off * 2;
        uint32_t v_addr = smem_u32(Vh) + cur * VH_SZ * 2 + v_off * 2;

        float sacc[8][4];
#pragma unroll
        for (int s = 0; s < 8; s++)
#pragma unroll
            for (int i = 0; i < 4; i++) sacc[s][i] = 0.f;

#pragma unroll
        for (int ks = 0; ks < 4; ks++) {
            uint32_t qa[4];
            LDSM_X4(qa[0], qa[1], qa[2], qa[3], q_addr + ks * 32);
#pragma unroll
            for (int np = 0; np < 4; np++) {
                uint32_t kb[4];
                LDSM_X4(kb[0], kb[1], kb[2], kb[3],
                        k_addr + np * (16 * HPITCH * 2) + ks * 32);
                MMA_F16(sacc[np * 2],     qa, kb[0], kb[1]);
                MMA_F16(sacc[np * 2 + 1], qa, kb[2], kb[3]);
            }
        }

        size_t abase = ((size_t)bh * SEQ + (size_t)(it * 128 + warp * 16)) * SEQ
                     + (size_t)jt * 64;
        uint32_t pa[4][4];
#pragma unroll
        for (int s = 0; s < 8; s++) {
            float p0 = ex2f(sacc[s][0]) * inv0;
            float p1 = ex2f(sacc[s][1]) * inv0;
            float p2 = ex2f(sacc[s][2]) * inv1;
            float p3 = ex2f(sacc[s][3]) * inv1;
            int cl = s * 8 + t4 * 2;
            *(float2*)(attn + abase + (size_t)g * SEQ + cl)       = make_float2(p0, p1);
            *(float2*)(attn + abase + (size_t)(g + 8) * SEQ + cl) = make_float2(p2, p3);
            int ks = s >> 1;
            if ((s & 1) == 0) {
                pa[ks][0] = pack_h2(p0, p1);
                pa[ks][1] = pack_h2(p2, p3);
            } else {
                pa[ks][2] = pack_h2(p0, p1);
                pa[ks][3] = pack_h2(p2, p3);
            }
        }

#pragma unroll
        for (int ks = 0; ks < 4; ks++) {
#pragma unroll
            for (int np = 0; np < 4; np++) {
                uint32_t vb[4];
                LDSM_X4_T(vb[0], vb[1], vb[2], vb[3],
                          v_addr + ks * (16 * HPITCH * 2) + np * 32);
                MMA_F16(oacc[np * 2],     pa[ks], vb[0], vb[1]);
                MMA_F16(oacc[np * 2 + 1], pa[ks], vb[2], vb[3]);
            }
        }
        __syncthreads();
        if (jt + 2 < 32) { issueK(jt + 2, cur); issueV(jt + 2, cur); CP_COMMIT(); }
    }

    // ---- write g_ao (normalized, fp16) ----
    int row0 = it * 128 + warp * 16 + g;
    size_t obase0 = (size_t)(b * SEQ + row0) * D_MODEL + h * 64;
    size_t obase1 = obase0 + (size_t)8 * D_MODEL;
#pragma unroll
    for (int s = 0; s < 8; s++) {
        int cl = s * 8 + t4 * 2;
        *(uint32_t*)(g_ao + obase0 + cl) = pack_h2(oacc[s][0], oacc[s][1]);
        *(uint32_t*)(g_ao + obase1 + cl) = pack_h2(oacc[s][2], oacc[s][3]);
    }
}

// ---------------- launch ----------------
extern "C" void kernel_launch(void* const* d_in, const int* in_sizes, int n_in,
                              void* d_out, int out_size) {
    const float* x     = (const float*)d_in[0];
    const float* gamma = (const float*)d_in[1];
    const float* beta  = (const float*)d_in[2];
    const float* Wqkv  = (const float*)d_in[3];
    const float* Wout  = (const float*)d_in[4];
    float* out  = (float*)d_out;
    float* attn = out + (size_t)ROWS * D_MODEL;

    __half *p_xn, *p_wqkv, *p_wout, *p_qkv, *p_ao;
    cudaGetSymbolAddress((void**)&p_xn,   g_xn);
    cudaGetSymbolAddress((void**)&p_wqkv, g_wqkv);
    cudaGetSymbolAddress((void**)&p_wout, g_wout);
    cudaGetSymbolAddress((void**)&p_qkv,  g_qkv);
    cudaGetSymbolAddress((void**)&p_ao,   g_ao);

    cudaFuncSetAttribute(attn_tc, cudaFuncAttributeMaxDynamicSharedMemorySize, ATT_SMEM);
    cudaFuncSetAttribute(gemm_f16<1>, cudaFuncAttributeMaxDynamicSharedMemorySize, GEMM_SMEM);
    cudaFuncSetAttribute(gemm_f16<0>, cudaFuncAttributeMaxDynamicSharedMemorySize, GEMM_SMEM);

    // 1) LayerNorm (fp16 out) + weight converts
    ln_kernel<<<ROWS, 256>>>(x, gamma, beta);
    cvt_kernel<<<(D_MODEL * 3 * D_MODEL) / (256 * 8), 256>>>(Wqkv, p_wqkv);
    cvt_kernel<<<(D_MODEL * D_MODEL) / (256 * 8), 256>>>(Wout, p_wout);
    // 2) QKV GEMM (fp16 MMA, fp16 out, BK=32 3-stage; Q cols pre-scaled)
    gemm_f16<1><<<dim3(3 * D_MODEL / 128, ROWS / 128), 256, GEMM_SMEM>>>(
        p_xn, p_wqkv, p_qkv, ROWS, 3 * D_MODEL, D_MODEL);
    // 3) two-pass fp16 attention (normalized attn + O; ex2 softmax; occ 2)
    attn_tc<<<dim3(SEQ / 128, NBH), 256, ATT_SMEM>>>(attn);
    // 4) out projection (fp16 MMA, fp32 out)
    gemm_f16<0><<<dim3(D_MODEL / 128, ROWS / 128), 256, GEMM_SMEM>>>(
        p_ao, p_wout, out, ROWS, D_MODEL, D_MODEL);
}

// round 17
// speedup vs baseline: 1.1477x; 1.0068x over previous
#include <cuda_runtime.h>
#include <cuda_fp16.h>
#include <math.h>
#include <stdint.h>

#define D_MODEL 1024
#define NHEAD   16
#define DH      64
#define SEQ     2048
#define BATCH   2
#define ROWS    (BATCH * SEQ)       // 4096
#define NBH     (BATCH * NHEAD)     // 32

// Q pre-scale: 0.125 * log2(e)  (softmax scale folded into Q, exp -> ex2)
#define QSCALE 0.18033688011112042f

// ---------------- scratch (static device arrays; no allocations) ----------------
__device__ __half g_xn[ROWS * D_MODEL];          // LN output (fp16)
__device__ __half g_wqkv[D_MODEL * 3 * D_MODEL]; // fp16 weights [K][N]
__device__ __half g_wout[D_MODEL * D_MODEL];     // fp16 weights [K][N]
__device__ __half g_qkv[ROWS * 3 * D_MODEL];     // QKV (fp16; Q pre-scaled)
__device__ __half g_ao[ROWS * D_MODEL];          // attn output (fp16)

__device__ __forceinline__ uint32_t pack_h2(float a, float b) {
    __half2 h = __floats2half2_rn(a, b);
    return *(uint32_t*)&h;
}
__device__ __forceinline__ uint32_t smem_u32(const void* p) {
    return (uint32_t)__cvta_generic_to_shared(p);
}
__device__ __forceinline__ uint32_t h2exp2_u(uint32_t x) {
    uint32_t y;
    asm("ex2.approx.f16x2 %0, %1;" : "=r"(y) : "r"(x));
    return y;
}
__device__ __forceinline__ float2 h2_to_f2(uint32_t h) {
    __half2 hh = *(__half2*)&h;
    return __half22float2(hh);
}

#define MMA_F16(c, a, b0, b1)                                                      \
    asm volatile("mma.sync.aligned.m16n8k16.row.col.f32.f16.f16.f32 "              \
                 "{%0,%1,%2,%3}, {%4,%5,%6,%7}, {%8,%9}, {%0,%1,%2,%3};\n"         \
                 : "+f"((c)[0]), "+f"((c)[1]), "+f"((c)[2]), "+f"((c)[3])          \
                 : "r"((a)[0]), "r"((a)[1]), "r"((a)[2]), "r"((a)[3]),             \
                   "r"(b0), "r"(b1))

#define LDSM_X4(r0, r1, r2, r3, addr)                                              \
    asm volatile("ldmatrix.sync.aligned.m8n8.x4.shared.b16 {%0,%1,%2,%3}, [%4];"   \
                 : "=r"(r0), "=r"(r1), "=r"(r2), "=r"(r3) : "r"(addr))

#define LDSM_X4_T(r0, r1, r2, r3, addr)                                            \
    asm volatile("ldmatrix.sync.aligned.m8n8.x4.trans.shared.b16 {%0,%1,%2,%3}, [%4];" \
                 : "=r"(r0), "=r"(r1), "=r"(r2), "=r"(r3) : "r"(addr))

#define CP16(dst, src)                                                             \
    asm volatile("cp.async.cg.shared.global [%0], [%1], 16;" :: "r"(dst), "l"(src))
#define CP_COMMIT() asm volatile("cp.async.commit_group;" ::: "memory")
#define CP_WAIT2()  asm volatile("cp.async.wait_group 2;" ::: "memory")
#define CP_WAIT1()  asm volatile("cp.async.wait_group 1;" ::: "memory")
#define CP_WAIT0()  asm volatile("cp.async.wait_group 0;" ::: "memory")

// ---------------- fp32 -> fp16 weight convert ----------------
__global__ void __launch_bounds__(256) cvt_kernel(const float* __restrict__ src,
                                                  __half* __restrict__ dst) {
    size_t i = ((size_t)blockIdx.x * 256 + threadIdx.x) * 8;
    float4 v0 = *(const float4*)(src + i);
    float4 v1 = *(const float4*)(src + i + 4);
    uint4 h;
    h.x = pack_h2(v0.x, v0.y);
    h.y = pack_h2(v0.z, v0.w);
    h.z = pack_h2(v1.x, v1.y);
    h.w = pack_h2(v1.z, v1.w);
    *(uint4*)(dst + i) = h;
}

// ---------------- LayerNorm (fp16 out) ----------------
__global__ void __launch_bounds__(256) ln_kernel(const float* __restrict__ x,
                                                 const float* __restrict__ gamma,
                                                 const float* __restrict__ beta) {
    int row = blockIdx.x;
    int tid = threadIdx.x;
    const float4* xr = (const float4*)(x + (size_t)row * D_MODEL);
    float4 v = xr[tid];
    float s  = v.x + v.y + v.z + v.w;
    float ss = v.x * v.x + v.y * v.y + v.z * v.z + v.w * v.w;

    __shared__ float reds[8], redss[8], bcast[2];
    for (int o = 16; o; o >>= 1) {
        s  += __shfl_down_sync(0xFFFFFFFFu, s, o);
        ss += __shfl_down_sync(0xFFFFFFFFu, ss, o);
    }
    int wid = tid >> 5, lid = tid & 31;
    if (lid == 0) { reds[wid] = s; redss[wid] = ss; }
    __syncthreads();
    if (tid == 0) {
        float ts = 0.f, tss = 0.f;
        for (int i = 0; i < 8; i++) { ts += reds[i]; tss += redss[i]; }
        float mu  = ts * (1.0f / D_MODEL);
        float var = tss * (1.0f / D_MODEL) - mu * mu;
        bcast[0] = mu;
        bcast[1] = rsqrtf(var + 1e-5f);
    }
    __syncthreads();
    float mu = bcast[0], r = bcast[1];
    float4 gg = ((const float4*)gamma)[tid];
    float4 bb = ((const float4*)beta)[tid];
    uint2 hh;
    hh.x = pack_h2((v.x - mu) * r * gg.x + bb.x, (v.y - mu) * r * gg.y + bb.y);
    hh.y = pack_h2((v.z - mu) * r * gg.z + bb.z, (v.w - mu) * r * gg.w + bb.w);
    ((uint2*)(g_xn + (size_t)row * D_MODEL))[tid] = hh;
}

// ---------------- fp16 tensor-core GEMM, BK=32, 3-stage cp.async ----------------
#define APITCH 40
#define BPITCH 136
#define AS_STG (128 * APITCH)
#define BS_STG (32 * BPITCH)
#define GEMM_SMEM ((3 * AS_STG + 3 * BS_STG) * 2)

template <int HALF_OUT>
__global__ void __launch_bounds__(256, 2) gemm_f16(const __half* __restrict__ A,
                                                   const __half* __restrict__ B,
                                                   void* __restrict__ Cv,
                                                   int M, int N, int K) {
    extern __shared__ __half smg[];
    __half* As = smg;
    __half* Bs = smg + 3 * AS_STG;

    int tid  = threadIdx.x;
    int warp = tid >> 5, lane = tid & 31;
    int wm = warp >> 2, wn = warp & 3;
    int g  = lane >> 2, t4 = lane & 3;
    int l8 = lane & 7, seg = lane >> 3;
    int bm = blockIdx.y * 128, bn = blockIdx.x * 128;

    float acc[4][4][4];
#pragma unroll
    for (int f = 0; f < 4; f++)
#pragma unroll
        for (int q = 0; q < 4; q++)
#pragma unroll
            for (int i = 0; i < 4; i++) acc[f][q][i] = 0.f;

    int ar0 = tid >> 2;
    int ac0 = (tid & 3) * 8;
    int br0 = tid >> 4;
    int bc0 = (tid & 15) * 8;
    const __half* Ap = A + (size_t)(bm + ar0) * K + ac0;
    const __half* Bp = B + (size_t)br0 * N + bn + bc0;

    uint32_t as_dst = smem_u32(As) + (ar0 * APITCH + ac0) * 2;
    uint32_t bs_dst = smem_u32(Bs) + (br0 * BPITCH + bc0) * 2;

    auto issue = [&](int kt, int buf) {
        const __half* Ap2 = Ap + kt * 32;
        const __half* Bp2 = Bp + (size_t)kt * 32 * N;
        uint32_t ad = as_dst + buf * AS_STG * 2;
        uint32_t bd = bs_dst + buf * BS_STG * 2;
        CP16(ad, Ap2);
        CP16(ad + 64 * APITCH * 2, Ap2 + (size_t)64 * K);
        CP16(bd, Bp2);
        CP16(bd + 16 * BPITCH * 2, Bp2 + (size_t)16 * N);
    };

    issue(0, 0); CP_COMMIT();
    issue(1, 1); CP_COMMIT();

    uint32_t a_base_off = ((wm * 64 + (seg & 1) * 8 + l8) * APITCH + (seg >> 1) * 8) * 2;
    uint32_t b_base_off = (((seg & 1) * 8 + l8) * BPITCH + wn * 32 + (seg >> 1) * 8) * 2;

    int NT = K >> 5;
    int cur = 0, nxt2 = 2;
    for (int kt = 0; kt < NT; kt++) {
        if (kt + 1 < NT) CP_WAIT1(); else CP_WAIT0();
        __syncthreads();
        if (kt + 2 < NT) { issue(kt + 2, nxt2); CP_COMMIT(); }

        uint32_t a_addr = smem_u32(As) + cur * AS_STG * 2 + a_base_off;
        uint32_t b_addr = smem_u32(Bs) + cur * BS_STG * 2 + b_base_off;
#pragma unroll
        for (int ks = 0; ks < 2; ks++) {
            uint32_t af[4][4], bf[2][4];
#pragma unroll
            for (int f = 0; f < 4; f++)
                LDSM_X4(af[f][0], af[f][1], af[f][2], af[f][3],
                        a_addr + (f * 16 * APITCH + ks * 16) * 2);
#pragma unroll
            for (int qq = 0; qq < 2; qq++)
                LDSM_X4_T(bf[qq][0], bf[qq][1], bf[qq][2], bf[qq][3],
                          b_addr + (ks * 16 * BPITCH + qq * 16) * 2);
#pragma unroll
            for (int f = 0; f < 4; f++)
#pragma unroll
                for (int q = 0; q < 4; q++)
                    MMA_F16(acc[f][q], af[f], bf[q >> 1][(q & 1) * 2],
                            bf[q >> 1][(q & 1) * 2 + 1]);
        }
        cur = (cur == 2) ? 0 : cur + 1;
        nxt2 = (nxt2 == 2) ? 0 : nxt2 + 1;
    }

    float cs = 1.0f;
    if (HALF_OUT && bn < 1024) cs = QSCALE;
#pragma unroll
    for (int f = 0; f < 4; f++) {
        int r0 = bm + wm * 64 + f * 16 + g;
#pragma unroll
        for (int q = 0; q < 4; q++) {
            int c = bn + wn * 32 + q * 8 + t4 * 2;
            if (HALF_OUT) {
                __half* C = (__half*)Cv;
                *(uint32_t*)&C[(size_t)r0 * N + c] =
                    pack_h2(acc[f][q][0] * cs, acc[f][q][1] * cs);
                *(uint32_t*)&C[(size_t)(r0 + 8) * N + c] =
                    pack_h2(acc[f][q][2] * cs, acc[f][q][3] * cs);
            } else {
                float* C = (float*)Cv;
                *(float2*)&C[(size_t)r0 * N + c] = make_float2(acc[f][q][0], acc[f][q][1]);
                *(float2*)&C[(size_t)(r0 + 8) * N + c] =
                    make_float2(acc[f][q][2], acc[f][q][3]);
            }
        }
    }
}

// ---------------- fp16 two-pass attention, 2 CTAs/SM ----------------
// Phase A: 4-stage K pipeline (reuses V buffers), 1 sync/jt, f16x2 exp.
// Phase B: 2-stage K+V, f16x2 exp. Q pre-scaled -> p = ex2(sacc).
#define HPITCH 72
#define QH_SZ  (128 * HPITCH)
#define KH_SZ  (64 * HPITCH)
#define VH_SZ  (64 * HPITCH)
#define ATT_SMEM ((QH_SZ + 2 * KH_SZ + 2 * VH_SZ) * 2)

__global__ void __launch_bounds__(256, 2) attn_tc(float* __restrict__ attn) {
    extern __shared__ __half smh[];
    __half* Qh = smh;                    // [128][72]
    __half* Kh = smh + QH_SZ;            // [2][64][72] (phase A: [4] stages incl. V space)
    __half* Vh = Kh + 2 * KH_SZ;         // [2][64][72]

    int it = blockIdx.x;
    int bh = blockIdx.y;
    int b = bh >> 4, h = bh & 15;
    int tid = threadIdx.x;
    int warp = tid >> 5, lane = tid & 31;
    int g = lane >> 2, t4 = lane & 3;
    int l8 = lane & 7, seg = lane >> 3;

    size_t qkv_b = (size_t)(b * SEQ) * 3072;

    // stage Q tile [128][64]
    {
        int r  = tid >> 1;
        int c0 = (tid & 1) * 32;
        const __half* src = g_qkv + qkv_b + (size_t)(it * 128 + r) * 3072 + h * 64 + c0;
        __half* dst = Qh + r * HPITCH + c0;
#pragma unroll
        for (int c = 0; c < 32; c += 8)
            *(uint4*)(dst + c) = *(const uint4*)(src + c);
    }

    int ldr = tid >> 3;
    int ldc = (tid & 7) * 8;
    const __half* Kbase = g_qkv + qkv_b + 1024 + h * 64;
    const __half* Vbase = g_qkv + qkv_b + 2048 + h * 64;

    uint32_t k_dst = smem_u32(Kh) + (ldr * HPITCH + ldc) * 2;
    uint32_t v_dst = smem_u32(Vh) + (ldr * HPITCH + ldc) * 2;

    auto issueK = [&](int jt, int buf) {   // buf 0..3 in phase A (K+V space), 0..1 in B
        const __half* src = Kbase + (size_t)(jt * 64 + ldr) * 3072 + ldc;
        uint32_t d = k_dst + buf * KH_SZ * 2;
        CP16(d, src);
        CP16(d + 32 * HPITCH * 2, src + (size_t)32 * 3072);
    };
    auto issueV = [&](int jt, int buf) {
        const __half* src = Vbase + (size_t)(jt * 64 + ldr) * 3072 + ldc;
        uint32_t d = v_dst + buf * VH_SZ * 2;
        CP16(d, src);
        CP16(d + 32 * HPITCH * 2, src + (size_t)32 * 3072);
    };

    int q_off = (warp * 16 + (seg & 1) * 8 + l8) * HPITCH + (seg >> 1) * 8;
    int k_off = ((seg >> 1) * 8 + l8) * HPITCH + (seg & 1) * 8;
    int v_off = ((seg & 1) * 8 + l8) * HPITCH + (seg >> 1) * 8;
    uint32_t q_addr = smem_u32(Qh) + q_off * 2;

    // ======== Phase A: row sums (K only), 4-stage, 1 sync/jt ========
    issueK(0, 0); CP_COMMIT();
    issueK(1, 1); CP_COMMIT();
    issueK(2, 2); CP_COMMIT();

    float lsum0 = 0.f, lsum1 = 0.f;

#pragma unroll 1
    for (int jt = 0; jt < 32; jt++) {
        if (jt < 30) CP_WAIT2(); else if (jt == 30) CP_WAIT1(); else CP_WAIT0();
        __syncthreads();
        if (jt + 3 < 32) { issueK(jt + 3, (jt + 3) & 3); CP_COMMIT(); }

        uint32_t k_addr = smem_u32(Kh) + (jt & 3) * KH_SZ * 2 + k_off * 2;
        float sacc[8][4];
#pragma unroll
        for (int s = 0; s < 8; s++)
#pragma unroll
            for (int i = 0; i < 4; i++) sacc[s][i] = 0.f;

#pragma unroll
        for (int ks = 0; ks < 4; ks++) {
            uint32_t qa[4];
            LDSM_X4(qa[0], qa[1], qa[2], qa[3], q_addr + ks * 32);
#pragma unroll
            for (int np = 0; np < 4; np++) {
                uint32_t kb[4];
                LDSM_X4(kb[0], kb[1], kb[2], kb[3],
                        k_addr + np * (16 * HPITCH * 2) + ks * 32);
                MMA_F16(sacc[np * 2],     qa, kb[0], kb[1]);
                MMA_F16(sacc[np * 2 + 1], qa, kb[2], kb[3]);
            }
        }
#pragma unroll
        for (int s = 0; s < 8; s++) {
            float2 f01 = h2_to_f2(h2exp2_u(pack_h2(sacc[s][0], sacc[s][1])));
            float2 f23 = h2_to_f2(h2exp2_u(pack_h2(sacc[s][2], sacc[s][3])));
            lsum0 += f01.x + f01.y;
            lsum1 += f23.x + f23.y;
        }
    }

    lsum0 += __shfl_xor_sync(0xFFFFFFFFu, lsum0, 1);
    lsum0 += __shfl_xor_sync(0xFFFFFFFFu, lsum0, 2);
    lsum1 += __shfl_xor_sync(0xFFFFFFFFu, lsum1, 1);
    lsum1 += __shfl_xor_sync(0xFFFFFFFFu, lsum1, 2);
    float inv0 = 1.0f / lsum0;
    float inv1 = 1.0f / lsum1;

    __syncthreads();   // phase A reads fully done before phase B overwrites buffers

    // ======== Phase B: normalized store + PV (2-stage K+V) ========
    issueK(0, 0); issueV(0, 0); CP_COMMIT();
    issueK(1, 1); issueV(1, 1); CP_COMMIT();

    float oacc[8][4];
#pragma unroll
    for (int s = 0; s < 8; s++)
#pragma unroll
        for (int i = 0; i < 4; i++) oacc[s][i] = 0.f;

#pragma unroll 1
    for (int jt = 0; jt < 32; jt++) {
        int cur = jt & 1;
        if (jt + 1 < 32) CP_WAIT1(); else CP_WAIT0();
        __syncthreads();

        uint32_t k_addr = smem_u32(Kh) + cur * KH_SZ * 2 + k_off * 2;
        uint32_t v_addr = smem_u32(Vh) + cur * VH_SZ * 2 + v_off * 2;

        float sacc[8][4];
#pragma unroll
        for (int s = 0; s < 8; s++)
#pragma unroll
            for (int i = 0; i < 4; i++) sacc[s][i] = 0.f;

#pragma unroll
        for (int ks = 0; ks < 4; ks++) {
            uint32_t qa[4];
            LDSM_X4(qa[0], qa[1], qa[2], qa[3], q_addr + ks * 32);
#pragma unroll
            for (int np = 0; np < 4; np++) {
                uint32_t kb[4];
                LDSM_X4(kb[0], kb[1], kb[2], kb[3],
                        k_addr + np * (16 * HPITCH * 2) + ks * 32);
                MMA_F16(sacc[np * 2],     qa, kb[0], kb[1]);
                MMA_F16(sacc[np * 2 + 1], qa, kb[2], kb[3]);
            }
        }

        size_t abase = ((size_t)bh * SEQ + (size_t)(it * 128 + warp * 16)) * SEQ
                     + (size_t)jt * 64;
        uint32_t pa[4][4];
#pragma unroll
        for (int s = 0; s < 8; s++) {
            float2 f01 = h2_to_f2(h2exp2_u(pack_h2(sacc[s][0], sacc[s][1])));
            float2 f23 = h2_to_f2(h2exp2_u(pack_h2(sacc[s][2], sacc[s][3])));
            float p0 = f01.x * inv0;
            float p1 = f01.y * inv0;
            float p2 = f23.x * inv1;
            float p3 = f23.y * inv1;
            int cl = s * 8 + t4 * 2;
            *(float2*)(attn + abase + (size_t)g * SEQ + cl)       = make_float2(p0, p1);
            *(float2*)(attn + abase + (size_t)(g + 8) * SEQ + cl) = make_float2(p2, p3);
            int ks = s >> 1;
            if ((s & 1) == 0) {
                pa[ks][0] = pack_h2(p0, p1);
                pa[ks][1] = pack_h2(p2, p3);
            } else {
                pa[ks][2] = pack_h2(p0, p1);
                pa[ks][3] = pack_h2(p2, p3);
            }
        }

#pragma unroll
        for (int ks = 0; ks < 4; ks++) {
#pragma unroll
            for (int np = 0; np < 4; np++) {
                uint32_t vb[4];
                LDSM_X4_T(vb[0], vb[1], vb[2], vb[3],
                          v_addr + ks * (16 * HPITCH * 2) + np * 32);
                MMA_F16(oacc[np * 2],     pa[ks], vb[0], vb[1]);
                MMA_F16(oacc[np * 2 + 1], pa[ks], vb[2], vb[3]);
            }
        }
        __syncthreads();
        if (jt + 2 < 32) { issueK(jt + 2, cur); issueV(jt + 2, cur); CP_COMMIT(); }
    }

    // ---- write g_ao (normalized, fp16) ----
    int row0 = it * 128 + warp * 16 + g;
    size_t obase0 = (size_t)(b * SEQ + row0) * D_MODEL + h * 64;
    size_t obase1 = obase0 + (size_t)8 * D_MODEL;
#pragma unroll
    for (int s = 0; s < 8; s++) {
        int cl = s * 8 + t4 * 2;
        *(uint32_t*)(g_ao + obase0 + cl) = pack_h2(oacc[s][0], oacc[s][1]);
        *(uint32_t*)(g_ao + obase1 + cl) = pack_h2(oacc[s][2], oacc[s][3]);
    }
}

// ---------------- launch ----------------
extern "C" void kernel_launch(void* const* d_in, const int* in_sizes, int n_in,
                              void* d_out, int out_size) {
    const float* x     = (const float*)d_in[0];
    const float* gamma = (const float*)d_in[1];
    const float* beta  = (const float*)d_in[2];
    const float* Wqkv  = (const float*)d_in[3];
    const float* Wout  = (const float*)d_in[4];
    float* out  = (float*)d_out;
    float* attn = out + (size_t)ROWS * D_MODEL;

    __half *p_xn, *p_wqkv, *p_wout, *p_qkv, *p_ao;
    cudaGetSymbolAddress((void**)&p_xn,   g_xn);
    cudaGetSymbolAddress((void**)&p_wqkv, g_wqkv);
    cudaGetSymbolAddress((void**)&p_wout, g_wout);
    cudaGetSymbolAddress((void**)&p_qkv,  g_qkv);
    cudaGetSymbolAddress((void**)&p_ao,   g_ao);

    cudaFuncSetAttribute(attn_tc, cudaFuncAttributeMaxDynamicSharedMemorySize, ATT_SMEM);
    cudaFuncSetAttribute(gemm_f16<1>, cudaFuncAttributeMaxDynamicSharedMemorySize, GEMM_SMEM);
    cudaFuncSetAttribute(gemm_f16<0>, cudaFuncAttributeMaxDynamicSharedMemorySize, GEMM_SMEM);

    // 1) LayerNorm (fp16 out) + weight converts
    ln_kernel<<<ROWS, 256>>>(x, gamma, beta);
    cvt_kernel<<<(D_MODEL * 3 * D_MODEL) / (256 * 8), 256>>>(Wqkv, p_wqkv);
    cvt_kernel<<<(D_MODEL * D_MODEL) / (256 * 8), 256>>>(Wout, p_wout);
    // 2) QKV GEMM (fp16 MMA, fp16 out, BK=32 3-stage; Q cols pre-scaled)
    gemm_f16<1><<<dim3(3 * D_MODEL / 128, ROWS / 128), 256, GEMM_SMEM>>>(
        p_xn, p_wqkv, p_qkv, ROWS, 3 * D_MODEL, D_MODEL);
    // 3) two-pass fp16 attention (normalized attn + O; f16x2 ex2 softmax; occ 2)
    attn_tc<<<dim3(SEQ / 128, NBH), 256, ATT_SMEM>>>(attn);
    // 4) out projection (fp16 MMA, fp32 out)
    gemm_f16<0><<<dim3(D_MODEL / 128, ROWS / 128), 256, GEMM_SMEM>>>(
        p_ao, p_wout, out, ROWS, D_MODEL, D_MODEL);
}